// round 8
// baseline (speedup 1.0000x reference)
#include <cuda_runtime.h>
#include <cuda_bf16.h>
#include <cuda_fp16.h>
#include <cstdint>

#define N_NODES 50000
#define N_EDGES 800000
#define DIM 128

// ---------------- scratch (device globals; no allocation allowed) ----------------
__device__ int   g_cnt[N_NODES];
__device__ float g_dinv[N_NODES];
__device__ int   g_rowptr[N_NODES + 1];
__device__ int   g_slot[N_EDGES];
__device__ int   g_srcs[N_EDGES];
__device__ int   g_bsum[32];
// fp16 transformed messages (gather stream)
__device__ __align__(16) __half g_hwh[(size_t)N_NODES * DIM];
// bf16 hi/lo split inputs for layer-2 GEMM (produced by layer-1 agg)
__device__ __align__(16) __nv_bfloat16 g_x1hi[(size_t)N_NODES * DIM];
__device__ __align__(16) __nv_bfloat16 g_x1lo[(size_t)N_NODES * DIM];
// W^T hi/lo for both layers: [layer][c][k]
__device__ __align__(16) __nv_bfloat16 g_whi[2 * DIM * DIM];
__device__ __align__(16) __nv_bfloat16 g_wlo[2 * DIM * DIM];

// side stream + events for graph-level overlap (created at static init)
static cudaStream_t g_s2 = nullptr;
static cudaEvent_t  g_evA = nullptr, g_evB = nullptr;
namespace {
struct StreamInit {
    StreamInit() {
        cudaStreamCreateWithFlags(&g_s2, cudaStreamNonBlocking);
        cudaEventCreateWithFlags(&g_evA, cudaEventDisableTiming);
        cudaEventCreateWithFlags(&g_evB, cudaEventDisableTiming);
    }
};
StreamInit g_stream_init;
}

// scan geometry: 25 blocks x 512 threads x 4 elems = 51200 >= 50000
#define SCAN_B 25
#define SCAN_T 512
#define SCAN_CHUNK (SCAN_T * 4)

// ---------------- setup kernels ----------------
// 4 edges per thread; atomic count AND remember each edge's slot
__global__ void k_count(const int* __restrict__ ei) {
    int t = blockIdx.x * blockDim.x + threadIdx.x;
    int e = t * 4;
    if (e >= N_EDGES) return;
    int4 d = *(const int4*)(ei + N_EDGES + e);
    int4 s;
    s.x = atomicAdd(&g_cnt[d.x], 1);
    s.y = atomicAdd(&g_cnt[d.y], 1);
    s.z = atomicAdd(&g_cnt[d.z], 1);
    s.w = atomicAdd(&g_cnt[d.w], 1);
    *(int4*)(g_slot + e) = s;
}

// Phase A: per-block local exclusive scan of g_cnt into g_rowptr; block totals; dinv.
__global__ void __launch_bounds__(SCAN_T) k_scan_a() {
    __shared__ int warp_sums[SCAN_T / 32];
    int tid  = threadIdx.x;
    int lane = tid & 31;
    int wid  = tid >> 5;
    int base = blockIdx.x * SCAN_CHUNK + tid * 4;

    int4 v = make_int4(0, 0, 0, 0);
    if (base + 3 < N_NODES) {
        v = *(const int4*)(g_cnt + base);
    } else {
        if (base + 0 < N_NODES) v.x = g_cnt[base + 0];
        if (base + 1 < N_NODES) v.y = g_cnt[base + 1];
        if (base + 2 < N_NODES) v.z = g_cnt[base + 2];
        if (base + 3 < N_NODES) v.w = g_cnt[base + 3];
    }
    // fused dinv (degree includes self loop)
    if (base + 0 < N_NODES) g_dinv[base + 0] = rsqrtf((float)(v.x + 1));
    if (base + 1 < N_NODES) g_dinv[base + 1] = rsqrtf((float)(v.y + 1));
    if (base + 2 < N_NODES) g_dinv[base + 2] = rsqrtf((float)(v.z + 1));
    if (base + 3 < N_NODES) g_dinv[base + 3] = rsqrtf((float)(v.w + 1));

    int t0 = v.x, t1 = t0 + v.y, t2 = t1 + v.z, t3 = t2 + v.w;

    int s = t3;
    #pragma unroll
    for (int off = 1; off < 32; off <<= 1) {
        int n = __shfl_up_sync(0xffffffffu, s, off);
        if (lane >= off) s += n;
    }
    if (lane == 31) warp_sums[wid] = s;
    __syncthreads();

    if (wid == 0) {
        int ws = (lane < SCAN_T / 32) ? warp_sums[lane] : 0;
        int w = ws;
        #pragma unroll
        for (int off = 1; off < 32; off <<= 1) {
            int n = __shfl_up_sync(0xffffffffu, w, off);
            if (lane >= off) w += n;
        }
        if (lane < SCAN_T / 32) warp_sums[lane] = w - ws;
        if (lane == SCAN_T / 32 - 1) g_bsum[blockIdx.x] = w;
    }
    __syncthreads();

    int thread_excl = warp_sums[wid] + (s - t3);
    if (base + 0 < N_NODES) g_rowptr[base + 0] = thread_excl;
    if (base + 1 < N_NODES) g_rowptr[base + 1] = thread_excl + t0;
    if (base + 2 < N_NODES) g_rowptr[base + 2] = thread_excl + t1;
    if (base + 3 < N_NODES) g_rowptr[base + 3] = thread_excl + t2;
}

// Phase C (fused B): compute own block offset from g_bsum; add.
__global__ void __launch_bounds__(SCAN_T) k_scan_c() {
    __shared__ int s_off;
    if (threadIdx.x < 32) {
        int l = threadIdx.x;
        int v = (l < SCAN_B) ? g_bsum[l] : 0;
        int s = v;
        #pragma unroll
        for (int off = 1; off < 32; off <<= 1) {
            int n = __shfl_up_sync(0xffffffffu, s, off);
            if (l >= off) s += n;
        }
        if (l == blockIdx.x) s_off = s - v;  // exclusive
    }
    __syncthreads();
    int off  = s_off;
    int base = blockIdx.x * SCAN_CHUNK + threadIdx.x * 4;
    #pragma unroll
    for (int j = 0; j < 4; j++) {
        int i = base + j;
        if (i < N_NODES) g_rowptr[i] += off;
    }
    if (blockIdx.x == 0 && threadIdx.x == 0) g_rowptr[N_NODES] = N_EDGES;
}

// atomic-free fill: slot was recorded in k_count
__global__ void k_fill(const int* __restrict__ ei) {
    int t = blockIdx.x * blockDim.x + threadIdx.x;
    int e = t * 4;
    if (e >= N_EDGES) return;
    int4 s  = *(const int4*)(ei + e);
    int4 d  = *(const int4*)(ei + N_EDGES + e);
    int4 sl = *(const int4*)(g_slot + e);
    g_srcs[g_rowptr[d.x] + sl.x] = s.x;
    g_srcs[g_rowptr[d.y] + sl.y] = s.y;
    g_srcs[g_rowptr[d.z] + sl.z] = s.z;
    g_srcs[g_rowptr[d.w] + sl.w] = s.w;
}

// ---------------- conversions ----------------
__device__ __forceinline__ void split_store(float v, __nv_bfloat16* hi, __nv_bfloat16* lo) {
    __nv_bfloat16 h = __float2bfloat16(v);
    *hi = h;
    *lo = __float2bfloat16(v - __bfloat162float(h));
}

// W1, W2 (f32, [k][c]) -> transposed hi/lo [layer][c][k]
__global__ void __launch_bounds__(128) k_cvt_w(const float* __restrict__ W1,
                                               const float* __restrict__ W2) {
    int layer = blockIdx.x >> 7;
    int c     = blockIdx.x & 127;
    int k     = threadIdx.x;
    const float* W = layer ? W2 : W1;
    float v = W[k * DIM + c];
    __nv_bfloat16 h, l;
    split_store(v, &h, &l);
    g_whi[layer * DIM * DIM + c * DIM + k] = h;
    g_wlo[layer * DIM * DIM + c * DIM + k] = l;
}

// ---------------- mma.sync GEMM ----------------
// SCALE=true:  Yh[r,:] = fp16((X[r,:] @ W) * dinv[r])   (layer 2)
// SCALE=false: Yh[r,:] = fp16(X[r,:] @ W)                (layer 1; no dinv dep)
#define TILE_M   128
#define SPITCH   136
#define TILE_BYT (TILE_M * SPITCH * 2)
#define OFF_AH   0
#define OFF_AL   (TILE_BYT)
#define OFF_BH   (2 * TILE_BYT)
#define OFF_BL   (3 * TILE_BYT)
#define GEMM_SMEM (4 * TILE_BYT)

__device__ __forceinline__ void mma_bf16(float* c, const uint32_t* a, const uint32_t* b) {
    asm volatile(
        "mma.sync.aligned.m16n8k16.row.col.f32.bf16.bf16.f32 "
        "{%0,%1,%2,%3}, {%4,%5,%6,%7}, {%8,%9}, {%0,%1,%2,%3};"
        : "+f"(c[0]), "+f"(c[1]), "+f"(c[2]), "+f"(c[3])
        : "r"(a[0]), "r"(a[1]), "r"(a[2]), "r"(a[3]), "r"(b[0]), "r"(b[1]));
}

static __device__ __forceinline__ void stage_tile(
    __nv_bfloat16* dst, const __nv_bfloat16* __restrict__ src,
    int row0, int row_limit, int tid)
{
    #pragma unroll
    for (int it = 0; it < 8; it++) {
        int i   = (it * 256 + tid) * 8;
        int row = i >> 7;
        int col = i & 127;
        uint4 v = make_uint4(0, 0, 0, 0);
        int gr = row0 + row;
        if (gr < row_limit)
            v = *(const uint4*)(src + (size_t)gr * DIM + col);
        *(uint4*)(dst + row * SPITCH + col) = v;
    }
}

static __device__ __forceinline__ void stage_tile_f32(
    __nv_bfloat16* dstH, __nv_bfloat16* dstL, const float* __restrict__ src,
    int row0, int tid)
{
    #pragma unroll
    for (int it = 0; it < 16; it++) {
        int i   = (it * 256 + tid) * 4;
        int row = i >> 7;
        int col = i & 127;
        float4 v = make_float4(0.f, 0.f, 0.f, 0.f);
        int gr = row0 + row;
        if (gr < N_NODES)
            v = *(const float4*)(src + (size_t)gr * DIM + col);
        ushort4 hv, lv;
        __nv_bfloat16 h, l;
        split_store(v.x, &h, &l); hv.x = __bfloat16_as_ushort(h); lv.x = __bfloat16_as_ushort(l);
        split_store(v.y, &h, &l); hv.y = __bfloat16_as_ushort(h); lv.y = __bfloat16_as_ushort(l);
        split_store(v.z, &h, &l); hv.z = __bfloat16_as_ushort(h); lv.z = __bfloat16_as_ushort(l);
        split_store(v.w, &h, &l); hv.w = __bfloat16_as_ushort(h); lv.w = __bfloat16_as_ushort(l);
        *(ushort4*)((unsigned short*)dstH + row * SPITCH + col) = hv;
        *(ushort4*)((unsigned short*)dstL + row * SPITCH + col) = lv;
    }
}

template <bool F32IN, bool SCALE>
__global__ void __launch_bounds__(256) k_gemm_mma(
    const void* __restrict__ xin, const __nv_bfloat16* __restrict__ xlo,
    const __nv_bfloat16* __restrict__ whi, const __nv_bfloat16* __restrict__ wlo,
    __half* __restrict__ Y)
{
    extern __shared__ char sm[];
    __nv_bfloat16* Ah = (__nv_bfloat16*)(sm + OFF_AH);
    __nv_bfloat16* Al = (__nv_bfloat16*)(sm + OFF_AL);
    __nv_bfloat16* Bh = (__nv_bfloat16*)(sm + OFF_BH);
    __nv_bfloat16* Bl = (__nv_bfloat16*)(sm + OFF_BL);

    int tid  = threadIdx.x;
    int wid  = tid >> 5;
    int lane = tid & 31;
    int row0 = blockIdx.x * TILE_M;

    if (F32IN) {
        stage_tile_f32(Ah, Al, (const float*)xin, row0, tid);
    } else {
        stage_tile(Ah, (const __nv_bfloat16*)xin, row0, N_NODES, tid);
        stage_tile(Al, xlo, row0, N_NODES, tid);
    }
    stage_tile(Bh, whi, 0, DIM, tid);
    stage_tile(Bl, wlo, 0, DIM, tid);
    __syncthreads();

    int g = lane >> 2;
    int t = lane & 3;

    float acc[16][4];
    #pragma unroll
    for (int i = 0; i < 16; i++)
        #pragma unroll
        for (int j = 0; j < 4; j++) acc[i][j] = 0.f;

    const __nv_bfloat16* arow0 = Ah + (wid * 16 + g) * SPITCH + t * 2;
    const __nv_bfloat16* arow8 = arow0 + 8 * SPITCH;
    const size_t alo_off = (size_t)(Al - Ah);

    #pragma unroll
    for (int ks = 0; ks < 8; ks++) {
        int kb = ks * 16;
        uint32_t ah[4], al[4];
        ah[0] = *(const uint32_t*)(arow0 + kb);
        ah[1] = *(const uint32_t*)(arow8 + kb);
        ah[2] = *(const uint32_t*)(arow0 + kb + 8);
        ah[3] = *(const uint32_t*)(arow8 + kb + 8);
        al[0] = *(const uint32_t*)(arow0 + alo_off + kb);
        al[1] = *(const uint32_t*)(arow8 + alo_off + kb);
        al[2] = *(const uint32_t*)(arow0 + alo_off + kb + 8);
        al[3] = *(const uint32_t*)(arow8 + alo_off + kb + 8);

        #pragma unroll
        for (int nb = 0; nb < 16; nb++) {
            const __nv_bfloat16* bp = Bh + (nb * 8 + g) * SPITCH + kb + t * 2;
            uint32_t bh[2], bl[2];
            bh[0] = *(const uint32_t*)(bp);
            bh[1] = *(const uint32_t*)(bp + 8);
            bl[0] = *(const uint32_t*)(bp + TILE_M * SPITCH);
            bl[1] = *(const uint32_t*)(bp + TILE_M * SPITCH + 8);
            mma_bf16(acc[nb], ah, bh);   // hi*hi
            mma_bf16(acc[nb], ah, bl);   // hi*lo
            mma_bf16(acc[nb], al, bh);   // lo*hi
        }
    }

    int r0 = row0 + wid * 16 + g;
    int r1 = r0 + 8;
    float d0 = 1.f, d1 = 1.f;
    if (SCALE) {
        d0 = (r0 < N_NODES) ? g_dinv[r0] : 0.f;
        d1 = (r1 < N_NODES) ? g_dinv[r1] : 0.f;
    }
    #pragma unroll
    for (int nb = 0; nb < 16; nb++) {
        int col = nb * 8 + t * 2;
        if (r0 < N_NODES) {
            __half2 h = __float22half2_rn(make_float2(acc[nb][0] * d0, acc[nb][1] * d0));
            *(__half2*)(Y + (size_t)r0 * DIM + col) = h;
        }
        if (r1 < N_NODES) {
            __half2 h = __float22half2_rn(make_float2(acc[nb][2] * d1, acc[nb][3] * d1));
            *(__half2*)(Y + (size_t)r1 * DIM + col) = h;
        }
    }
}

// ---------------- aggregation: one HALF-WARP per destination node ----------------
struct F8 { float4 a, b; };

__device__ __forceinline__ F8 h8_to_f8(uint4 u) {
    F8 r;
    float2 p0 = __half22float2(*(__half2*)&u.x);
    float2 p1 = __half22float2(*(__half2*)&u.y);
    float2 p2 = __half22float2(*(__half2*)&u.z);
    float2 p3 = __half22float2(*(__half2*)&u.w);
    r.a = make_float4(p0.x, p0.y, p1.x, p1.y);
    r.b = make_float4(p2.x, p2.y, p3.x, p3.y);
    return r;
}

__device__ __forceinline__ void fma_acc(F8& acc, const F8& v, float s) {
    acc.a.x = fmaf(v.a.x, s, acc.a.x); acc.a.y = fmaf(v.a.y, s, acc.a.y);
    acc.a.z = fmaf(v.a.z, s, acc.a.z); acc.a.w = fmaf(v.a.w, s, acc.a.w);
    acc.b.x = fmaf(v.b.x, s, acc.b.x); acc.b.y = fmaf(v.b.y, s, acc.b.y);
    acc.b.z = fmaf(v.b.z, s, acc.b.z); acc.b.w = fmaf(v.b.w, s, acc.b.w);
}

// EDGE_SCALE: hw is UNSCALED; multiply each gathered row by dinv[src].
template <bool SPLIT, bool EDGE_SCALE>
__global__ void __launch_bounds__(256) k_agg(const __half* __restrict__ hw,
                                             const float* __restrict__ b,
                                             float* __restrict__ outF,
                                             __nv_bfloat16* __restrict__ outHi,
                                             __nv_bfloat16* __restrict__ outLo) {
    int node   = (blockIdx.x * blockDim.x + threadIdx.x) >> 4;
    int lane16 = threadIdx.x & 15;
    if (node >= N_NODES) return;

    int beg = g_rowptr[node];
    int end = g_rowptr[node + 1];
    int col = lane16 * 8;

    float dd = g_dinv[node];
    F8 acc;
    {
        F8 self = h8_to_f8(*(const uint4*)(hw + (size_t)node * DIM + col));
        float s = EDGE_SCALE ? dd : 1.f;
        acc.a = make_float4(self.a.x * s, self.a.y * s, self.a.z * s, self.a.w * s);
        acc.b = make_float4(self.b.x * s, self.b.y * s, self.b.z * s, self.b.w * s);
    }

    int e = beg;
    for (; e + 8 <= end; e += 8) {
        int   si[8];
        uint4 u[8];
        #pragma unroll
        for (int j = 0; j < 8; j++) si[j] = g_srcs[e + j];
        #pragma unroll
        for (int j = 0; j < 8; j++)
            u[j] = *(const uint4*)(hw + (size_t)si[j] * DIM + col);
        float ds[8];
        if (EDGE_SCALE) {
            #pragma unroll
            for (int j = 0; j < 8; j++) ds[j] = g_dinv[si[j]];
        }
        #pragma unroll
        for (int j = 0; j < 8; j++) {
            F8 v = h8_to_f8(u[j]);
            fma_acc(acc, v, EDGE_SCALE ? ds[j] : 1.f);
        }
    }
    if (e + 4 <= end) {
        int   si[4];
        uint4 u[4];
        #pragma unroll
        for (int j = 0; j < 4; j++) si[j] = g_srcs[e + j];
        #pragma unroll
        for (int j = 0; j < 4; j++)
            u[j] = *(const uint4*)(hw + (size_t)si[j] * DIM + col);
        float ds[4];
        if (EDGE_SCALE) {
            #pragma unroll
            for (int j = 0; j < 4; j++) ds[j] = g_dinv[si[j]];
        }
        #pragma unroll
        for (int j = 0; j < 4; j++) {
            F8 v = h8_to_f8(u[j]);
            fma_acc(acc, v, EDGE_SCALE ? ds[j] : 1.f);
        }
        e += 4;
    }
    for (; e < end; e++) {
        int s = g_srcs[e];
        F8 v = h8_to_f8(*(const uint4*)(hw + (size_t)s * DIM + col));
        fma_acc(acc, v, EDGE_SCALE ? g_dinv[s] : 1.f);
    }

    float4 bb0 = *(const float4*)(b + col);
    float4 bb1 = *(const float4*)(b + col + 4);
    float4 o0 = make_float4(acc.a.x * dd + bb0.x, acc.a.y * dd + bb0.y,
                            acc.a.z * dd + bb0.z, acc.a.w * dd + bb0.w);
    float4 o1 = make_float4(acc.b.x * dd + bb1.x, acc.b.y * dd + bb1.y,
                            acc.b.z * dd + bb1.z, acc.b.w * dd + bb1.w);
    if (SPLIT) {
        ushort4 hv0, lv0, hv1, lv1;
        __nv_bfloat16 h, l;
        split_store(o0.x, &h, &l); hv0.x = __bfloat16_as_ushort(h); lv0.x = __bfloat16_as_ushort(l);
        split_store(o0.y, &h, &l); hv0.y = __bfloat16_as_ushort(h); lv0.y = __bfloat16_as_ushort(l);
        split_store(o0.z, &h, &l); hv0.z = __bfloat16_as_ushort(h); lv0.z = __bfloat16_as_ushort(l);
        split_store(o0.w, &h, &l); hv0.w = __bfloat16_as_ushort(h); lv0.w = __bfloat16_as_ushort(l);
        split_store(o1.x, &h, &l); hv1.x = __bfloat16_as_ushort(h); lv1.x = __bfloat16_as_ushort(l);
        split_store(o1.y, &h, &l); hv1.y = __bfloat16_as_ushort(h); lv1.y = __bfloat16_as_ushort(l);
        split_store(o1.z, &h, &l); hv1.z = __bfloat16_as_ushort(h); lv1.z = __bfloat16_as_ushort(l);
        split_store(o1.w, &h, &l); hv1.w = __bfloat16_as_ushort(h); lv1.w = __bfloat16_as_ushort(l);
        unsigned short* ph = (unsigned short*)outHi + (size_t)node * DIM + col;
        unsigned short* pl = (unsigned short*)outLo + (size_t)node * DIM + col;
        *(ushort4*)(ph)     = hv0;
        *(ushort4*)(ph + 4) = hv1;
        *(ushort4*)(pl)     = lv0;
        *(ushort4*)(pl + 4) = lv1;
    } else {
        float* po = outF + (size_t)node * DIM + col;
        *(float4*)(po)     = o0;
        *(float4*)(po + 4) = o1;
    }
}

// ---------------- launch ----------------
extern "C" void kernel_launch(void* const* d_in, const int* in_sizes, int n_in,
                              void* d_out, int out_size) {
    const float* x  = (const float*)d_in[0];
    const int*   ei = (const int*)d_in[1];
    const float* W1 = (const float*)d_in[2];
    const float* b1 = (const float*)d_in[3];
    const float* W2 = (const float*)d_in[4];
    const float* b2 = (const float*)d_in[5];
    float* out = (float*)d_out;

    cudaFuncSetAttribute(k_gemm_mma<true, false>,
                         cudaFuncAttributeMaxDynamicSharedMemorySize, GEMM_SMEM);
    cudaFuncSetAttribute(k_gemm_mma<false, true>,
                         cudaFuncAttributeMaxDynamicSharedMemorySize, GEMM_SMEM);

    __half* hwh; cudaGetSymbolAddress((void**)&hwh, g_hwh);
    int*    cnt; cudaGetSymbolAddress((void**)&cnt, g_cnt);
    __nv_bfloat16 *x1h, *x1l, *wh, *wl;
    cudaGetSymbolAddress((void**)&x1h, g_x1hi);
    cudaGetSymbolAddress((void**)&x1l, g_x1lo);
    cudaGetSymbolAddress((void**)&wh, g_whi);
    cudaGetSymbolAddress((void**)&wl, g_wlo);

    const int TB = 256;
    int nb_edges4 = (N_EDGES / 4 + TB - 1) / TB;
    int nb_gemm   = (N_NODES + TILE_M - 1) / TILE_M;
    int nb_agg    = (N_NODES * 16 + TB - 1) / TB;

    bool overlap = (g_s2 != nullptr) && (g_evA != nullptr) && (g_evB != nullptr);

    if (overlap) {
        // fork at t=0: ENTIRE CSR setup on side stream; gemm1 (no dinv dep) on main
        cudaEventRecord(g_evA, 0);
        cudaStreamWaitEvent(g_s2, g_evA, 0);
        cudaMemsetAsync(cnt, 0, N_NODES * sizeof(int), g_s2);
        k_count<<<nb_edges4, TB, 0, g_s2>>>(ei);
        k_scan_a<<<SCAN_B, SCAN_T, 0, g_s2>>>();
        k_scan_c<<<SCAN_B, SCAN_T, 0, g_s2>>>();
        k_fill<<<nb_edges4, TB, 0, g_s2>>>(ei);
        cudaEventRecord(g_evB, g_s2);

        k_cvt_w<<<256, 128>>>(W1, W2);
        k_gemm_mma<true, false><<<nb_gemm, TB, GEMM_SMEM>>>(x, nullptr, wh, wl, hwh);

        cudaStreamWaitEvent(0, g_evB, 0);  // join before agg1
    } else {
        cudaMemsetAsync(cnt, 0, N_NODES * sizeof(int));
        k_count<<<nb_edges4, TB>>>(ei);
        k_scan_a<<<SCAN_B, SCAN_T>>>();
        k_scan_c<<<SCAN_B, SCAN_T>>>();
        k_fill<<<nb_edges4, TB>>>(ei);
        k_cvt_w<<<256, 128>>>(W1, W2);
        k_gemm_mma<true, false><<<nb_gemm, TB, GEMM_SMEM>>>(x, nullptr, wh, wl, hwh);
    }

    // layer 1 aggregation: per-edge dinv[src] scaling (hw unscaled)
    k_agg<true, true><<<nb_agg, TB>>>(hwh, b1, nullptr, x1h, x1l);

    // layer 2: gemm scales by dinv in epilogue; agg gathers prescaled rows
    k_gemm_mma<false, true><<<nb_gemm, TB, GEMM_SMEM>>>(x1h, x1l, wh + DIM * DIM, wl + DIM * DIM, hwh);
    k_agg<false, false><<<nb_agg, TB>>>(hwh, b2, out, nullptr, nullptr);
}

// round 9
// speedup vs baseline: 1.0716x; 1.0716x over previous
#include <cuda_runtime.h>
#include <cuda_bf16.h>
#include <cuda_fp16.h>
#include <cstdint>

#define N_NODES 50000
#define N_EDGES 800000
#define DIM 128

// ---------------- scratch (device globals; no allocation allowed) ----------------
__device__ int   g_cnt[N_NODES];          // zeroed by k_scan_a after use (self-cleaning)
__device__ float g_dinv[N_NODES];
__device__ int   g_rowptr[N_NODES + 1];
__device__ int   g_slot[N_EDGES];
__device__ int   g_srcs[N_EDGES];
__device__ int   g_bsum[32];
// fp16 transformed messages (gather stream)
__device__ __align__(16) __half g_hwh[(size_t)N_NODES * DIM];
// fp16 layer-1 output (= layer-2 GEMM input; exact bf16 hi/lo split done in-kernel)
__device__ __align__(16) __half g_x1h[(size_t)N_NODES * DIM];
// W^T hi/lo for both layers: [layer][c][k]
__device__ __align__(16) __nv_bfloat16 g_whi[2 * DIM * DIM];
__device__ __align__(16) __nv_bfloat16 g_wlo[2 * DIM * DIM];

// side stream + events for graph-level overlap (created at static init)
static cudaStream_t g_s2 = nullptr;
static cudaEvent_t  g_evA = nullptr, g_evB = nullptr;
namespace {
struct StreamInit {
    StreamInit() {
        cudaStreamCreateWithFlags(&g_s2, cudaStreamNonBlocking);
        cudaEventCreateWithFlags(&g_evA, cudaEventDisableTiming);
        cudaEventCreateWithFlags(&g_evB, cudaEventDisableTiming);
    }
};
StreamInit g_stream_init;
}

// scan geometry: 25 blocks x 512 threads x 4 elems = 51200 >= 50000
#define SCAN_B 25
#define SCAN_T 512
#define SCAN_CHUNK (SCAN_T * 4)

// ---------------- setup kernels ----------------
// 4 edges per thread; atomic count AND remember each edge's slot
__global__ void k_count(const int* __restrict__ ei) {
    int t = blockIdx.x * blockDim.x + threadIdx.x;
    int e = t * 4;
    if (e >= N_EDGES) return;
    int4 d = *(const int4*)(ei + N_EDGES + e);
    int4 s;
    s.x = atomicAdd(&g_cnt[d.x], 1);
    s.y = atomicAdd(&g_cnt[d.y], 1);
    s.z = atomicAdd(&g_cnt[d.z], 1);
    s.w = atomicAdd(&g_cnt[d.w], 1);
    *(int4*)(g_slot + e) = s;
}

// Phase A: per-block local exclusive scan of g_cnt into g_rowptr; block totals; dinv.
// Also RE-ZEROES g_cnt so the next kernel_launch (graph replay) starts clean.
__global__ void __launch_bounds__(SCAN_T) k_scan_a() {
    __shared__ int warp_sums[SCAN_T / 32];
    int tid  = threadIdx.x;
    int lane = tid & 31;
    int wid  = tid >> 5;
    int base = blockIdx.x * SCAN_CHUNK + tid * 4;

    int4 v = make_int4(0, 0, 0, 0);
    if (base + 3 < N_NODES) {
        v = *(const int4*)(g_cnt + base);
        *(int4*)(g_cnt + base) = make_int4(0, 0, 0, 0);   // self-clean
    } else {
        if (base + 0 < N_NODES) { v.x = g_cnt[base + 0]; g_cnt[base + 0] = 0; }
        if (base + 1 < N_NODES) { v.y = g_cnt[base + 1]; g_cnt[base + 1] = 0; }
        if (base + 2 < N_NODES) { v.z = g_cnt[base + 2]; g_cnt[base + 2] = 0; }
        if (base + 3 < N_NODES) { v.w = g_cnt[base + 3]; g_cnt[base + 3] = 0; }
    }
    // fused dinv (degree includes self loop)
    if (base + 0 < N_NODES) g_dinv[base + 0] = rsqrtf((float)(v.x + 1));
    if (base + 1 < N_NODES) g_dinv[base + 1] = rsqrtf((float)(v.y + 1));
    if (base + 2 < N_NODES) g_dinv[base + 2] = rsqrtf((float)(v.z + 1));
    if (base + 3 < N_NODES) g_dinv[base + 3] = rsqrtf((float)(v.w + 1));

    int t0 = v.x, t1 = t0 + v.y, t2 = t1 + v.z, t3 = t2 + v.w;

    int s = t3;
    #pragma unroll
    for (int off = 1; off < 32; off <<= 1) {
        int n = __shfl_up_sync(0xffffffffu, s, off);
        if (lane >= off) s += n;
    }
    if (lane == 31) warp_sums[wid] = s;
    __syncthreads();

    if (wid == 0) {
        int ws = (lane < SCAN_T / 32) ? warp_sums[lane] : 0;
        int w = ws;
        #pragma unroll
        for (int off = 1; off < 32; off <<= 1) {
            int n = __shfl_up_sync(0xffffffffu, w, off);
            if (lane >= off) w += n;
        }
        if (lane < SCAN_T / 32) warp_sums[lane] = w - ws;
        if (lane == SCAN_T / 32 - 1) g_bsum[blockIdx.x] = w;
    }
    __syncthreads();

    int thread_excl = warp_sums[wid] + (s - t3);
    if (base + 0 < N_NODES) g_rowptr[base + 0] = thread_excl;
    if (base + 1 < N_NODES) g_rowptr[base + 1] = thread_excl + t0;
    if (base + 2 < N_NODES) g_rowptr[base + 2] = thread_excl + t1;
    if (base + 3 < N_NODES) g_rowptr[base + 3] = thread_excl + t2;
}

// Phase C (fused B): compute own block offset from g_bsum; add.
__global__ void __launch_bounds__(SCAN_T) k_scan_c() {
    __shared__ int s_off;
    if (threadIdx.x < 32) {
        int l = threadIdx.x;
        int v = (l < SCAN_B) ? g_bsum[l] : 0;
        int s = v;
        #pragma unroll
        for (int off = 1; off < 32; off <<= 1) {
            int n = __shfl_up_sync(0xffffffffu, s, off);
            if (l >= off) s += n;
        }
        if (l == blockIdx.x) s_off = s - v;  // exclusive
    }
    __syncthreads();
    int off  = s_off;
    int base = blockIdx.x * SCAN_CHUNK + threadIdx.x * 4;
    #pragma unroll
    for (int j = 0; j < 4; j++) {
        int i = base + j;
        if (i < N_NODES) g_rowptr[i] += off;
    }
    if (blockIdx.x == 0 && threadIdx.x == 0) g_rowptr[N_NODES] = N_EDGES;
}

// atomic-free fill: slot was recorded in k_count
__global__ void k_fill(const int* __restrict__ ei) {
    int t = blockIdx.x * blockDim.x + threadIdx.x;
    int e = t * 4;
    if (e >= N_EDGES) return;
    int4 s  = *(const int4*)(ei + e);
    int4 d  = *(const int4*)(ei + N_EDGES + e);
    int4 sl = *(const int4*)(g_slot + e);
    g_srcs[g_rowptr[d.x] + sl.x] = s.x;
    g_srcs[g_rowptr[d.y] + sl.y] = s.y;
    g_srcs[g_rowptr[d.z] + sl.z] = s.z;
    g_srcs[g_rowptr[d.w] + sl.w] = s.w;
}

// ---------------- conversions ----------------
__device__ __forceinline__ void split_store(float v, __nv_bfloat16* hi, __nv_bfloat16* lo) {
    __nv_bfloat16 h = __float2bfloat16(v);
    *hi = h;
    *lo = __float2bfloat16(v - __bfloat162float(h));
}

// W1, W2 (f32, [k][c]) -> transposed hi/lo [layer][c][k]
__global__ void __launch_bounds__(128) k_cvt_w(const float* __restrict__ W1,
                                               const float* __restrict__ W2) {
    int layer = blockIdx.x >> 7;
    int c     = blockIdx.x & 127;
    int k     = threadIdx.x;
    const float* W = layer ? W2 : W1;
    float v = W[k * DIM + c];
    __nv_bfloat16 h, l;
    split_store(v, &h, &l);
    g_whi[layer * DIM * DIM + c * DIM + k] = h;
    g_wlo[layer * DIM * DIM + c * DIM + k] = l;
}

// ---------------- mma.sync GEMM: Yh[r,:] = fp16((X[r,:] @ W) * dinv[r]) ----------------
#define TILE_M   128
#define SPITCH   136
#define TILE_BYT (TILE_M * SPITCH * 2)
#define OFF_AH   0
#define OFF_AL   (TILE_BYT)
#define OFF_BH   (2 * TILE_BYT)
#define OFF_BL   (3 * TILE_BYT)
#define GEMM_SMEM (4 * TILE_BYT)

__device__ __forceinline__ void mma_bf16(float* c, const uint32_t* a, const uint32_t* b) {
    asm volatile(
        "mma.sync.aligned.m16n8k16.row.col.f32.bf16.bf16.f32 "
        "{%0,%1,%2,%3}, {%4,%5,%6,%7}, {%8,%9}, {%0,%1,%2,%3};"
        : "+f"(c[0]), "+f"(c[1]), "+f"(c[2]), "+f"(c[3])
        : "r"(a[0]), "r"(a[1]), "r"(a[2]), "r"(a[3]), "r"(b[0]), "r"(b[1]));
}

static __device__ __forceinline__ void stage_tile(
    __nv_bfloat16* dst, const __nv_bfloat16* __restrict__ src,
    int row0, int row_limit, int tid)
{
    #pragma unroll
    for (int it = 0; it < 8; it++) {
        int i   = (it * 256 + tid) * 8;
        int row = i >> 7;
        int col = i & 127;
        uint4 v = make_uint4(0, 0, 0, 0);
        int gr = row0 + row;
        if (gr < row_limit)
            v = *(const uint4*)(src + (size_t)gr * DIM + col);
        *(uint4*)(dst + row * SPITCH + col) = v;
    }
}

// stage f32 source: split to hi/lo in registers
static __device__ __forceinline__ void stage_tile_f32(
    __nv_bfloat16* dstH, __nv_bfloat16* dstL, const float* __restrict__ src,
    int row0, int tid)
{
    #pragma unroll
    for (int it = 0; it < 16; it++) {
        int i   = (it * 256 + tid) * 4;
        int row = i >> 7;
        int col = i & 127;
        float4 v = make_float4(0.f, 0.f, 0.f, 0.f);
        int gr = row0 + row;
        if (gr < N_NODES)
            v = *(const float4*)(src + (size_t)gr * DIM + col);
        ushort4 hv, lv;
        __nv_bfloat16 h, l;
        split_store(v.x, &h, &l); hv.x = __bfloat16_as_ushort(h); lv.x = __bfloat16_as_ushort(l);
        split_store(v.y, &h, &l); hv.y = __bfloat16_as_ushort(h); lv.y = __bfloat16_as_ushort(l);
        split_store(v.z, &h, &l); hv.z = __bfloat16_as_ushort(h); lv.z = __bfloat16_as_ushort(l);
        split_store(v.w, &h, &l); hv.w = __bfloat16_as_ushort(h); lv.w = __bfloat16_as_ushort(l);
        *(ushort4*)((unsigned short*)dstH + row * SPITCH + col) = hv;
        *(ushort4*)((unsigned short*)dstL + row * SPITCH + col) = lv;
    }
}

// stage fp16 source: split to bf16 hi/lo in registers (EXACT: 11 mant bits -> 8 + rest)
static __device__ __forceinline__ void stage_tile_f16(
    __nv_bfloat16* dstH, __nv_bfloat16* dstL, const __half* __restrict__ src,
    int row0, int tid)
{
    #pragma unroll
    for (int it = 0; it < 8; it++) {
        int i   = (it * 256 + tid) * 8;
        int row = i >> 7;
        int col = i & 127;
        uint4 u = make_uint4(0, 0, 0, 0);
        int gr = row0 + row;
        if (gr < N_NODES)
            u = *(const uint4*)(src + (size_t)gr * DIM + col);
        const __half* hp = (const __half*)&u;
        ushort4 hv0, lv0, hv1, lv1;
        __nv_bfloat16 h, l;
        split_store(__half2float(hp[0]), &h, &l); hv0.x = __bfloat16_as_ushort(h); lv0.x = __bfloat16_as_ushort(l);
        split_store(__half2float(hp[1]), &h, &l); hv0.y = __bfloat16_as_ushort(h); lv0.y = __bfloat16_as_ushort(l);
        split_store(__half2float(hp[2]), &h, &l); hv0.z = __bfloat16_as_ushort(h); lv0.z = __bfloat16_as_ushort(l);
        split_store(__half2float(hp[3]), &h, &l); hv0.w = __bfloat16_as_ushort(h); lv0.w = __bfloat16_as_ushort(l);
        split_store(__half2float(hp[4]), &h, &l); hv1.x = __bfloat16_as_ushort(h); lv1.x = __bfloat16_as_ushort(l);
        split_store(__half2float(hp[5]), &h, &l); hv1.y = __bfloat16_as_ushort(h); lv1.y = __bfloat16_as_ushort(l);
        split_store(__half2float(hp[6]), &h, &l); hv1.z = __bfloat16_as_ushort(h); lv1.z = __bfloat16_as_ushort(l);
        split_store(__half2float(hp[7]), &h, &l); hv1.w = __bfloat16_as_ushort(h); lv1.w = __bfloat16_as_ushort(l);
        unsigned short* ph = (unsigned short*)dstH + row * SPITCH + col;
        unsigned short* pl = (unsigned short*)dstL + row * SPITCH + col;
        *(ushort4*)(ph)     = hv0;
        *(ushort4*)(ph + 4) = hv1;
        *(ushort4*)(pl)     = lv0;
        *(ushort4*)(pl + 4) = lv1;
    }
}

// IN: 0 = f32 input, 1 = fp16 input. Epilogue always scales by dinv.
template <int IN>
__global__ void __launch_bounds__(256) k_gemm_mma(
    const void* __restrict__ xin,
    const __nv_bfloat16* __restrict__ whi, const __nv_bfloat16* __restrict__ wlo,
    __half* __restrict__ Y)
{
    extern __shared__ char sm[];
    __nv_bfloat16* Ah = (__nv_bfloat16*)(sm + OFF_AH);
    __nv_bfloat16* Al = (__nv_bfloat16*)(sm + OFF_AL);
    __nv_bfloat16* Bh = (__nv_bfloat16*)(sm + OFF_BH);
    __nv_bfloat16* Bl = (__nv_bfloat16*)(sm + OFF_BL);

    int tid  = threadIdx.x;
    int wid  = tid >> 5;
    int lane = tid & 31;
    int row0 = blockIdx.x * TILE_M;

    if (IN == 0) stage_tile_f32(Ah, Al, (const float*)xin, row0, tid);
    else         stage_tile_f16(Ah, Al, (const __half*)xin, row0, tid);
    stage_tile(Bh, whi, 0, DIM, tid);
    stage_tile(Bl, wlo, 0, DIM, tid);
    __syncthreads();

    int g = lane >> 2;
    int t = lane & 3;

    float acc[16][4];
    #pragma unroll
    for (int i = 0; i < 16; i++)
        #pragma unroll
        for (int j = 0; j < 4; j++) acc[i][j] = 0.f;

    const __nv_bfloat16* arow0 = Ah + (wid * 16 + g) * SPITCH + t * 2;
    const __nv_bfloat16* arow8 = arow0 + 8 * SPITCH;
    const size_t alo_off = (size_t)(Al - Ah);

    #pragma unroll
    for (int ks = 0; ks < 8; ks++) {
        int kb = ks * 16;
        uint32_t ah[4], al[4];
        ah[0] = *(const uint32_t*)(arow0 + kb);
        ah[1] = *(const uint32_t*)(arow8 + kb);
        ah[2] = *(const uint32_t*)(arow0 + kb + 8);
        ah[3] = *(const uint32_t*)(arow8 + kb + 8);
        al[0] = *(const uint32_t*)(arow0 + alo_off + kb);
        al[1] = *(const uint32_t*)(arow8 + alo_off + kb);
        al[2] = *(const uint32_t*)(arow0 + alo_off + kb + 8);
        al[3] = *(const uint32_t*)(arow8 + alo_off + kb + 8);

        #pragma unroll
        for (int nb = 0; nb < 16; nb++) {
            const __nv_bfloat16* bp = Bh + (nb * 8 + g) * SPITCH + kb + t * 2;
            uint32_t bh[2], bl[2];
            bh[0] = *(const uint32_t*)(bp);
            bh[1] = *(const uint32_t*)(bp + 8);
            bl[0] = *(const uint32_t*)(bp + TILE_M * SPITCH);
            bl[1] = *(const uint32_t*)(bp + TILE_M * SPITCH + 8);
            mma_bf16(acc[nb], ah, bh);   // hi*hi
            mma_bf16(acc[nb], ah, bl);   // hi*lo
            mma_bf16(acc[nb], al, bh);   // lo*hi
        }
    }

    int r0 = row0 + wid * 16 + g;
    int r1 = r0 + 8;
    float d0 = (r0 < N_NODES) ? g_dinv[r0] : 0.f;
    float d1 = (r1 < N_NODES) ? g_dinv[r1] : 0.f;
    #pragma unroll
    for (int nb = 0; nb < 16; nb++) {
        int col = nb * 8 + t * 2;
        if (r0 < N_NODES) {
            __half2 h = __float22half2_rn(make_float2(acc[nb][0] * d0, acc[nb][1] * d0));
            *(__half2*)(Y + (size_t)r0 * DIM + col) = h;
        }
        if (r1 < N_NODES) {
            __half2 h = __float22half2_rn(make_float2(acc[nb][2] * d1, acc[nb][3] * d1));
            *(__half2*)(Y + (size_t)r1 * DIM + col) = h;
        }
    }
}

// ---------------- aggregation: one HALF-WARP per destination node ----------------
struct F8 { float4 a, b; };

__device__ __forceinline__ F8 h8_to_f8(uint4 u) {
    F8 r;
    float2 p0 = __half22float2(*(__half2*)&u.x);
    float2 p1 = __half22float2(*(__half2*)&u.y);
    float2 p2 = __half22float2(*(__half2*)&u.z);
    float2 p3 = __half22float2(*(__half2*)&u.w);
    r.a = make_float4(p0.x, p0.y, p1.x, p1.y);
    r.b = make_float4(p2.x, p2.y, p3.x, p3.y);
    return r;
}

__device__ __forceinline__ void add_acc(F8& acc, const F8& v) {
    acc.a.x += v.a.x; acc.a.y += v.a.y; acc.a.z += v.a.z; acc.a.w += v.a.w;
    acc.b.x += v.b.x; acc.b.y += v.b.y; acc.b.z += v.b.z; acc.b.w += v.b.w;
}

// out[node,:] = (sum_src hw[src,:] + hw[node,:]) * dinv[node] + b
// OUTF16: emit fp16 (layer 1 -> layer-2 GEMM input). Else f32 (final output).
template <bool OUTF16>
__global__ void __launch_bounds__(256) k_agg(const __half* __restrict__ hw,
                                             const float* __restrict__ b,
                                             float* __restrict__ outF,
                                             __half* __restrict__ outH) {
    int node   = (blockIdx.x * blockDim.x + threadIdx.x) >> 4;
    int lane16 = threadIdx.x & 15;
    if (node >= N_NODES) return;

    int beg = g_rowptr[node];
    int end = g_rowptr[node + 1];
    int col = lane16 * 8;

    F8 acc = h8_to_f8(*(const uint4*)(hw + (size_t)node * DIM + col));  // self loop

    int e = beg;
    for (; e + 8 <= end; e += 8) {
        uint4 u[8];
        #pragma unroll
        for (int j = 0; j < 8; j++) {
            int s = g_srcs[e + j];
            u[j] = *(const uint4*)(hw + (size_t)s * DIM + col);
        }
        #pragma unroll
        for (int j = 0; j < 8; j++) {
            F8 v = h8_to_f8(u[j]);
            add_acc(acc, v);
        }
    }
    if (e + 4 <= end) {
        uint4 u[4];
        #pragma unroll
        for (int j = 0; j < 4; j++) {
            int s = g_srcs[e + j];
            u[j] = *(const uint4*)(hw + (size_t)s * DIM + col);
        }
        #pragma unroll
        for (int j = 0; j < 4; j++) {
            F8 v = h8_to_f8(u[j]);
            add_acc(acc, v);
        }
        e += 4;
    }
    for (; e < end; e++) {
        int s = g_srcs[e];
        F8 v = h8_to_f8(*(const uint4*)(hw + (size_t)s * DIM + col));
        add_acc(acc, v);
    }

    float d = g_dinv[node];
    float4 bb0 = *(const float4*)(b + col);
    float4 bb1 = *(const float4*)(b + col + 4);
    float4 o0 = make_float4(acc.a.x * d + bb0.x, acc.a.y * d + bb0.y,
                            acc.a.z * d + bb0.z, acc.a.w * d + bb0.w);
    float4 o1 = make_float4(acc.b.x * d + bb1.x, acc.b.y * d + bb1.y,
                            acc.b.z * d + bb1.z, acc.b.w * d + bb1.w);
    if (OUTF16) {
        uint4 u;
        __half2* up = (__half2*)&u;
        up[0] = __float22half2_rn(make_float2(o0.x, o0.y));
        up[1] = __float22half2_rn(make_float2(o0.z, o0.w));
        up[2] = __float22half2_rn(make_float2(o1.x, o1.y));
        up[3] = __float22half2_rn(make_float2(o1.z, o1.w));
        *(uint4*)(outH + (size_t)node * DIM + col) = u;
    } else {
        float* po = outF + (size_t)node * DIM + col;
        *(float4*)(po)     = o0;
        *(float4*)(po + 4) = o1;
    }
}

// ---------------- launch ----------------
extern "C" void kernel_launch(void* const* d_in, const int* in_sizes, int n_in,
                              void* d_out, int out_size) {
    const float* x  = (const float*)d_in[0];
    const int*   ei = (const int*)d_in[1];
    const float* W1 = (const float*)d_in[2];
    const float* b1 = (const float*)d_in[3];
    const float* W2 = (const float*)d_in[4];
    const float* b2 = (const float*)d_in[5];
    float* out = (float*)d_out;

    cudaFuncSetAttribute(k_gemm_mma<0>, cudaFuncAttributeMaxDynamicSharedMemorySize, GEMM_SMEM);
    cudaFuncSetAttribute(k_gemm_mma<1>, cudaFuncAttributeMaxDynamicSharedMemorySize, GEMM_SMEM);

    __half* hwh; cudaGetSymbolAddress((void**)&hwh, g_hwh);
    __half* x1h; cudaGetSymbolAddress((void**)&x1h, g_x1h);
    __nv_bfloat16 *wh, *wl;
    cudaGetSymbolAddress((void**)&wh, g_whi);
    cudaGetSymbolAddress((void**)&wl, g_wlo);

    const int TB = 256;
    int nb_edges4 = (N_EDGES / 4 + TB - 1) / TB;
    int nb_gemm   = (N_NODES + TILE_M - 1) / TILE_M;
    int nb_agg    = (N_NODES * 16 + TB - 1) / TB;

    bool overlap = (g_s2 != nullptr) && (g_evA != nullptr) && (g_evB != nullptr);

    // Common prefix on main stream (g_cnt is pre-zeroed: module init / scan_a self-clean)
    k_count<<<nb_edges4, TB>>>(ei);
    k_scan_a<<<SCAN_B, SCAN_T>>>();

    if (overlap) {
        // fork: side stream finalizes CSR while main runs cvt_w + gemm1
        cudaEventRecord(g_evA, 0);
        cudaStreamWaitEvent(g_s2, g_evA, 0);
        k_scan_c<<<SCAN_B, SCAN_T, 0, g_s2>>>();
        k_fill<<<nb_edges4, TB, 0, g_s2>>>(ei);
        cudaEventRecord(g_evB, g_s2);

        k_cvt_w<<<256, 128>>>(W1, W2);
        k_gemm_mma<0><<<nb_gemm, TB, GEMM_SMEM>>>(x, wh, wl, hwh);

        cudaStreamWaitEvent(0, g_evB, 0);  // join before agg1
    } else {
        k_scan_c<<<SCAN_B, SCAN_T>>>();
        k_fill<<<nb_edges4, TB>>>(ei);
        k_cvt_w<<<256, 128>>>(W1, W2);
        k_gemm_mma<0><<<nb_gemm, TB, GEMM_SMEM>>>(x, wh, wl, hwh);
    }

    // layer 1 aggregation -> fp16
    k_agg<true><<<nb_agg, TB>>>(hwh, b1, nullptr, x1h);

    // layer 2
    k_gemm_mma<1><<<nb_gemm, TB, GEMM_SMEM>>>(x1h, wh + DIM * DIM, wl + DIM * DIM, hwh);
    k_agg<false><<<nb_agg, TB>>>(hwh, b2, out, nullptr);
}